// round 4
// baseline (speedup 1.0000x reference)
#include <cuda_runtime.h>
#include <cstdint>

// ---------------------------------------------------------------------------
// QuantumDMRGLayer on GB300 (sm_103a)
//
// left  chain: 97 steps, carry_new(128) = [xi0*c | xi1*c](256) @ Wl[s](256x128)
// right chain: 96 steps (reverse order), inner 128x128 blocks transposed
// final      : out[b,l] = sum_n right[b,n] * ( A_lab[b,:] @ WL_l )[b,n]
//              with A_lab[b,(p,m)] = xl[b,p]*left[b,m]
//
// All GEMMs: mma.sync.m16n8k8 tf32, fp32 accumulate. Every tf32 operand is
// RN-rounded exactly once (weights in prep kernels, carries in epilogues) to
// avoid the hardware's RZ truncation bias compounding over 193 steps.
// ---------------------------------------------------------------------------

#define BATCH    8192
#define DIMVEC   196
#define XROW     (DIMVEC * 2)      // 392 floats per batch row of x
#define MDIM     128
#define NLSTEPS  97
#define NRSTEPS  96
#define WSTEP    (256 * MDIM)      // 32768 floats per step weight matrix

#define APITCH   260               // A smem pitch: (260 % 32 == 4) -> conflict-free frags
#define WPITCH   136               // W smem pitch: (136 % 32 == 8) -> conflict-free frags
#define RPITCH   132

static const int SMEM_SCAN  = (128 * APITCH + 2 * 32 * WPITCH) * 4;                       // 167,936
static const int SMEM_FINAL = (64 * APITCH + 2 * 32 * WPITCH + 64 * RPITCH + 64 * 4) * 4; // 136,192

// -------------------- device scratch (static: allocation-free) -------------
__device__ __align__(128) float g_wl  [NLSTEPS * WSTEP];   // [j][(s2,m)][n], tf32-rounded
__device__ __align__(128) float g_wr  [NRSTEPS * WSTEP];   // processing order j=0..95 == s=95..0, transposed, rounded
__device__ __align__(128) float g_wlab[10 * WSTEP];        // [l][(p,m)][n], rounded
__device__ __align__(128) float g_left [BATCH * MDIM];
__device__ __align__(128) float g_right[BATCH * MDIM];

// -------------------- helpers ----------------------------------------------
__device__ __forceinline__ float tf32r(float v) {
    uint32_t u;
    asm("cvt.rna.tf32.f32 %0, %1;" : "=r"(u) : "f"(v));
    return __uint_as_float(u);
}

__device__ __forceinline__ void mma_tf32(float d[4], const uint32_t a[4],
                                         uint32_t b0, uint32_t b1) {
    asm volatile(
        "mma.sync.aligned.m16n8k8.row.col.f32.tf32.tf32.f32 "
        "{%0,%1,%2,%3}, {%4,%5,%6,%7}, {%8,%9}, {%0,%1,%2,%3};\n"
        : "+f"(d[0]), "+f"(d[1]), "+f"(d[2]), "+f"(d[3])
        : "r"(a[0]), "r"(a[1]), "r"(a[2]), "r"(a[3]), "r"(b0), "r"(b1));
}

// Stage one 32(k) x 128(n) fp32 W slice into a padded smem buffer.
// 256 threads x 4 x 16B = 16 KB, perfectly coalesced.
__device__ __forceinline__ void stage32(float* dst, const float* __restrict__ src, int tid) {
#pragma unroll
    for (int i = 0; i < 4; i++) {
        int chunk = tid + i * 256;          // 0..1023
        int row   = chunk >> 5;             // 0..31
        int c     = (chunk & 31) * 4;       // 0..124
        uint32_t s = (uint32_t)__cvta_generic_to_shared(dst + row * WPITCH + c);
        asm volatile("cp.async.cg.shared.global [%0], [%1], 16;"
                     :: "r"(s), "l"(src + row * MDIM + c));
    }
    asm volatile("cp.async.commit_group;" ::: "memory");
}

// ======================= prep kernels ======================================
__global__ void prep_left_k(const float* __restrict__ src) {
    int i = (blockIdx.x * 256 + threadIdx.x) * 4;           // covers 97*256*128
    float4 v = *reinterpret_cast<const float4*>(src + i);
    v.x = tf32r(v.x); v.y = tf32r(v.y); v.z = tf32r(v.z); v.w = tf32r(v.w);
    *reinterpret_cast<float4*>(g_wl + i) = v;
}

// dst[((j*2+s2)*128+m)*128+n] = rn( src[(((95-j)*2+s2)*128+n)*128+m] )
__global__ void prep_right_k(const float* __restrict__ src) {
    int gid = blockIdx.x * 256 + threadIdx.x;               // dst float4 index
    int didx = gid * 4;
    int n  = didx & 127;
    int m  = (didx >> 7) & 127;
    int s2 = (didx >> 14) & 1;
    int j  = didx >> 15;
    int s  = 95 - j;
    const float* sb = src + (((size_t)(s * 2 + s2)) * 128) * 128 + m;  // + n*128 later
    float4 v;
    v.x = tf32r(__ldg(sb + (size_t)(n + 0) * 128));
    v.y = tf32r(__ldg(sb + (size_t)(n + 1) * 128));
    v.z = tf32r(__ldg(sb + (size_t)(n + 2) * 128));
    v.w = tf32r(__ldg(sb + (size_t)(n + 3) * 128));
    *reinterpret_cast<float4*>(g_wr + didx) = v;
}

// dst[l*WSTEP + (p*128+m)*128 + n] = rn( src[((p*128+m)*128+n)*10 + l] )
__global__ void prep_label_k(const float* __restrict__ src) {
    int gid = blockIdx.x * 256 + threadIdx.x;               // dst scalar index, 327,680
    int n = gid & 127;
    int m = (gid >> 7) & 127;
    int p = (gid >> 14) & 1;
    int l = gid >> 15;
    int sidx = ((p << 14) | (m << 7) | n) * 10 + l;
    g_wlab[gid] = tf32r(__ldg(src + sidx));
}

// ======================= scan kernel =======================================
// C-tile per CTA: 128(m) x 128(n), K = 256.  8 warps: wm in 0..3 (32 rows),
// wn in 0..1 (64 cols).  Per warp: acc[2][8][4] (2 m-subtiles x 8 n-subtiles).
__device__ __forceinline__ void compute_slice(const float* __restrict__ As,
                                              const float* __restrict__ Wb,
                                              int kb, float acc[2][8][4],
                                              int wm, int wn, int g, int t) {
    const uint32_t* Au = reinterpret_cast<const uint32_t*>(As);
    const uint32_t* Wu = reinterpret_cast<const uint32_t*>(Wb);
#pragma unroll
    for (int kk = 0; kk < 32; kk += 8) {
        uint32_t a[2][4];
#pragma unroll
        for (int i = 0; i < 2; i++) {
            int r = wm * 32 + i * 16 + g;
            int k = kb + kk + t;
            a[i][0] = Au[r * APITCH + k];
            a[i][1] = Au[(r + 8) * APITCH + k];
            a[i][2] = Au[r * APITCH + k + 4];
            a[i][3] = Au[(r + 8) * APITCH + k + 4];
        }
#pragma unroll
        for (int jj = 0; jj < 8; jj++) {
            int cn = wn * 64 + jj * 8 + g;
            uint32_t b0 = Wu[(kk + t) * WPITCH + cn];
            uint32_t b1 = Wu[(kk + t + 4) * WPITCH + cn];
            mma_tf32(acc[0][jj], a[0], b0, b1);
            mma_tf32(acc[1][jj], a[1], b0, b1);
        }
    }
}

__global__ __launch_bounds__(256, 1)
void scan_kernel(const float* __restrict__ x,
                 const float* __restrict__ w0,
                 const float* __restrict__ wend) {
    extern __shared__ float smem[];
    float* As = smem;                            // 128 x APITCH
    float* Wb0 = smem + 128 * APITCH;
    float* Wb1 = Wb0 + 32 * WPITCH;

    const bool is_left = blockIdx.x < 64;
    const int  b0 = (blockIdx.x & 63) * 128;
    const int  S  = is_left ? NLSTEPS : NRSTEPS;
    const float* Wg = is_left ? g_wl : g_wr;
    const float* iw = is_left ? w0 : wend;
    const int tid = threadIdx.x;

    // ---- init: carry = x[iv] @ iw (fp32 FMA), build A for step 0 ----
    {
        int r = tid & 127, half = tid >> 7;
        const float* xr = x + (size_t)(b0 + r) * XROW;
        int iv = is_left ? 0 : 195;
        int xi = is_left ? 1 : 194;
        float x0 = xr[iv * 2], x1 = xr[iv * 2 + 1];
        float xi0 = xr[xi * 2], xi1 = xr[xi * 2 + 1];
        for (int m = half * 64; m < half * 64 + 64; m++) {
            float v = x0 * iw[m] + x1 * iw[MDIM + m];
            As[r * APITCH + m]       = tf32r(xi0 * v);
            As[r * APITCH + 128 + m] = tf32r(xi1 * v);
        }
    }
    __syncthreads();

    const int warp = tid >> 5, lane = tid & 31, g = lane >> 2, t = lane & 3;
    const int wm = warp >> 1, wn = warp & 1;

    for (int j = 0; j < S; j++) {
        const float* W = Wg + (size_t)j * WSTEP;
        float acc[2][8][4];
#pragma unroll
        for (int i = 0; i < 2; i++)
#pragma unroll
            for (int jj = 0; jj < 8; jj++)
#pragma unroll
                for (int q = 0; q < 4; q++) acc[i][jj][q] = 0.f;

        stage32(Wb0, W, tid);
#pragma unroll 1
        for (int ks = 0; ks < 8; ks++) {
            float* cur = (ks & 1) ? Wb1 : Wb0;
            if (ks < 7) {
                float* nxt = (ks & 1) ? Wb0 : Wb1;
                stage32(nxt, W + (ks + 1) * 32 * MDIM, tid);
                asm volatile("cp.async.wait_group 1;" ::: "memory");
            } else {
                asm volatile("cp.async.wait_group 0;" ::: "memory");
            }
            __syncthreads();                      // slice ks visible to all warps
            compute_slice(As, cur, ks * 32, acc, wm, wn, g, t);
            __syncthreads();                      // all done reading before buffer/A reuse
        }

        if (j + 1 < S) {
            // epilogue: A <- tf32( xi(j+1) * carry_new )
            int xin = is_left ? (2 + j) : (193 - j);
#pragma unroll
            for (int i = 0; i < 2; i++) {
                int r0 = wm * 32 + i * 16 + g;
                const float* xr0 = x + (size_t)(b0 + r0) * XROW + xin * 2;
                const float* xr1 = x + (size_t)(b0 + r0 + 8) * XROW + xin * 2;
                float p00 = __ldg(xr0), p01 = __ldg(xr0 + 1);
                float p10 = __ldg(xr1), p11 = __ldg(xr1 + 1);
#pragma unroll
                for (int jj = 0; jj < 8; jj++) {
                    int c0 = wn * 64 + jj * 8 + 2 * t;
                    float d0 = acc[i][jj][0], d1 = acc[i][jj][1];
                    float d2 = acc[i][jj][2], d3 = acc[i][jj][3];
                    *(float2*)&As[r0 * APITCH + c0]             = make_float2(tf32r(p00 * d0), tf32r(p00 * d1));
                    *(float2*)&As[r0 * APITCH + 128 + c0]       = make_float2(tf32r(p01 * d0), tf32r(p01 * d1));
                    *(float2*)&As[(r0 + 8) * APITCH + c0]       = make_float2(tf32r(p10 * d2), tf32r(p10 * d3));
                    *(float2*)&As[(r0 + 8) * APITCH + 128 + c0] = make_float2(tf32r(p11 * d2), tf32r(p11 * d3));
                }
            }
            // epilogue->next-compute ordering provided by the sync inside ks=0
        } else {
            // final carry -> global (raw fp32)
            float* dst = is_left ? g_left : g_right;
#pragma unroll
            for (int i = 0; i < 2; i++) {
                int r0 = wm * 32 + i * 16 + g;
#pragma unroll
                for (int jj = 0; jj < 8; jj++) {
                    int c0 = wn * 64 + jj * 8 + 2 * t;
                    *(float2*)&dst[(size_t)(b0 + r0) * MDIM + c0]     = make_float2(acc[i][jj][0], acc[i][jj][1]);
                    *(float2*)&dst[(size_t)(b0 + r0 + 8) * MDIM + c0] = make_float2(acc[i][jj][2], acc[i][jj][3]);
                }
            }
        }
    }
}

// ======================= final kernel ======================================
// 128 CTAs x 64 batch rows. C-tile 64(m) x 128(n): 8 warps, wm in 0..1,
// wn in 0..3 (32 cols each). acc[2][4][4]. 10 label GEMMs + deterministic
// smem-tree reduction against right (no atomics).
__device__ __forceinline__ void compute_slice_f(const float* __restrict__ As,
                                                const float* __restrict__ Wb,
                                                int kb, float acc[2][4][4],
                                                int wm, int wn, int g, int t) {
    const uint32_t* Au = reinterpret_cast<const uint32_t*>(As);
    const uint32_t* Wu = reinterpret_cast<const uint32_t*>(Wb);
#pragma unroll
    for (int kk = 0; kk < 32; kk += 8) {
        uint32_t a[2][4];
#pragma unroll
        for (int i = 0; i < 2; i++) {
            int r = wm * 32 + i * 16 + g;
            int k = kb + kk + t;
            a[i][0] = Au[r * APITCH + k];
            a[i][1] = Au[(r + 8) * APITCH + k];
            a[i][2] = Au[r * APITCH + k + 4];
            a[i][3] = Au[(r + 8) * APITCH + k + 4];
        }
#pragma unroll
        for (int jj = 0; jj < 4; jj++) {
            int cn = wn * 32 + jj * 8 + g;
            uint32_t b0 = Wu[(kk + t) * WPITCH + cn];
            uint32_t b1 = Wu[(kk + t + 4) * WPITCH + cn];
            mma_tf32(acc[0][jj], a[0], b0, b1);
            mma_tf32(acc[1][jj], a[1], b0, b1);
        }
    }
}

__global__ __launch_bounds__(256, 1)
void final_kernel(const float* __restrict__ x, float* __restrict__ out) {
    extern __shared__ float smem[];
    float* As  = smem;                       // 64 x APITCH
    float* Wb0 = As + 64 * APITCH;
    float* Wb1 = Wb0 + 32 * WPITCH;
    float* sR  = Wb1 + 32 * WPITCH;          // 64 x RPITCH
    float* sP  = sR + 64 * RPITCH;           // 64 x 4 partials

    const int b0 = blockIdx.x * 64;
    const int tid = threadIdx.x;

    // build A_lab and stage right
    {
        int r = tid >> 2, q = tid & 3;
        const float* xr = x + (size_t)(b0 + r) * XROW + 98 * 2;
        float xl0 = __ldg(xr), xl1 = __ldg(xr + 1);
        for (int m = q * 32; m < q * 32 + 32; m++) {
            float v = g_left[(size_t)(b0 + r) * MDIM + m];
            As[r * APITCH + m]       = tf32r(xl0 * v);
            As[r * APITCH + 128 + m] = tf32r(xl1 * v);
            sR[r * RPITCH + m] = g_right[(size_t)(b0 + r) * MDIM + m];
        }
    }
    __syncthreads();

    const int warp = tid >> 5, lane = tid & 31, g = lane >> 2, t = lane & 3;
    const int wm = warp >> 2, wn = warp & 3;

    for (int l = 0; l < 10; l++) {
        const float* W = g_wlab + (size_t)l * WSTEP;
        float acc[2][4][4];
#pragma unroll
        for (int i = 0; i < 2; i++)
#pragma unroll
            for (int jj = 0; jj < 4; jj++)
#pragma unroll
                for (int q = 0; q < 4; q++) acc[i][jj][q] = 0.f;

        stage32(Wb0, W, tid);
#pragma unroll 1
        for (int ks = 0; ks < 8; ks++) {
            float* cur = (ks & 1) ? Wb1 : Wb0;
            if (ks < 7) {
                float* nxt = (ks & 1) ? Wb0 : Wb1;
                stage32(nxt, W + (ks + 1) * 32 * MDIM, tid);
                asm volatile("cp.async.wait_group 1;" ::: "memory");
            } else {
                asm volatile("cp.async.wait_group 0;" ::: "memory");
            }
            __syncthreads();
            compute_slice_f(As, cur, ks * 32, acc, wm, wn, g, t);
            __syncthreads();
        }

        // reduce: per (row, wn) partial = sum_cols acc * right
#pragma unroll
        for (int i = 0; i < 2; i++) {
            int r0 = wm * 32 + i * 16 + g;
            float p0 = 0.f, p1 = 0.f;
#pragma unroll
            for (int jj = 0; jj < 4; jj++) {
                int c0 = wn * 32 + jj * 8 + 2 * t;
                p0 += acc[i][jj][0] * sR[r0 * RPITCH + c0]
                    + acc[i][jj][1] * sR[r0 * RPITCH + c0 + 1];
                p1 += acc[i][jj][2] * sR[(r0 + 8) * RPITCH + c0]
                    + acc[i][jj][3] * sR[(r0 + 8) * RPITCH + c0 + 1];
            }
            p0 += __shfl_xor_sync(0xffffffffu, p0, 1);
            p0 += __shfl_xor_sync(0xffffffffu, p0, 2);
            p1 += __shfl_xor_sync(0xffffffffu, p1, 1);
            p1 += __shfl_xor_sync(0xffffffffu, p1, 2);
            if (t == 0) {
                sP[r0 * 4 + wn]       = p0;
                sP[(r0 + 8) * 4 + wn] = p1;
            }
        }
        __syncthreads();
        if (tid < 64) {
            float s = sP[tid * 4] + sP[tid * 4 + 1] + sP[tid * 4 + 2] + sP[tid * 4 + 3];
            out[(size_t)(b0 + tid) * 10 + l] = s;
        }
        __syncthreads();
    }
}

// ======================= launch ============================================
extern "C" void kernel_launch(void* const* d_in, const int* in_sizes, int n_in,
                              void* d_out, int out_size) {
    const float *x = nullptr, *w0 = nullptr, *wl = nullptr,
                *wlab = nullptr, *wr = nullptr, *wend = nullptr;
    for (int i = 0; i < n_in; i++) {
        const float* p = (const float*)d_in[i];
        switch (in_sizes[i]) {
            case 3211264: x = p; break;
            case 3178496: wl = p; break;
            case 327680:  wlab = p; break;
            case 3145728: wr = p; break;
            case 256:     if (!w0) w0 = p; else wend = p; break;
            default: break;
        }
    }
    if (!x || !w0 || !wl || !wlab || !wr || !wend) return;

    cudaFuncSetAttribute(scan_kernel,  cudaFuncAttributeMaxDynamicSharedMemorySize, SMEM_SCAN);
    cudaFuncSetAttribute(final_kernel, cudaFuncAttributeMaxDynamicSharedMemorySize, SMEM_FINAL);

    prep_left_k <<<3104, 256>>>(wl);
    prep_right_k<<<3072, 256>>>(wr);
    prep_label_k<<<1280, 256>>>(wlab);
    scan_kernel <<<128, 256, SMEM_SCAN>>>(x, w0, wend);
    final_kernel<<<128, 256, SMEM_FINAL>>>(x, (float*)d_out);
}